// round 12
// baseline (speedup 1.0000x reference)
#include <cuda_runtime.h>

// activation_moduleA: out[0:SIZE] = p = x[0:SIZE]
//                     out[SIZE:N] = weight * selu(p) + q,  q = x[SIZE:N]
// selu(v) = SCALE * (v > 0 ? v : ALPHA*(exp(v)-1))
//
// R11: L2-residency theory via SUPPORTED intrinsics (the inline-PTX evict
// hints of R6/R7 were unsupported on this stack).
//   x (p,q): __ldlu  - read-once, "last use" -> don't let x displace L2 lines
//   out:     __stcs  - streaming store, evict-first
//   w:       __ldg   - default allocate; the only sticky stream -> stays
//                      L2-resident across graph replays (L2 = 126 MB > 64 MB w,
//                      and L2 is NOT flushed at launch boundaries).
// Expected: steady-state DRAM traffic ~288 MB -> ~260 MB per replay.

#define SELU_SCALE 1.0507009873554804934193349852946f
#define SELU_ALPHA 1.6732632423543772848170429916717f

#define TPB 512

__device__ __forceinline__ float selu_f(float v) {
    float neg = SELU_ALPHA * expm1f(v);
    return SELU_SCALE * (v > 0.0f ? v : neg);
}

template <bool GUARD>
__global__ void __launch_bounds__(TPB)
activation_kernel(const float4* __restrict__ x,
                  const float4* __restrict__ w,
                  float4* __restrict__ out,
                  int size4)   // SIZE/4 float4 elements per half
{
    int i = blockIdx.x * TPB + threadIdx.x;
    if (GUARD && i >= size4) return;

    float4 p  = __ldlu(&x[i]);           // read-once: last-use hint
    float4 q  = __ldlu(&x[i + size4]);   // read-once: last-use hint
    float4 wv = __ldg(&w[i]);            // re-read every replay: let it cache

    // first half: straight copy of p (store issues while SELU computes)
    __stcs(&out[i], p);

    float4 r;
    r.x = fmaf(wv.x, selu_f(p.x), q.x);
    r.y = fmaf(wv.y, selu_f(p.y), q.y);
    r.z = fmaf(wv.z, selu_f(p.z), q.z);
    r.w = fmaf(wv.w, selu_f(p.w), q.w);
    __stcs(&out[i + size4], r);
}

extern "C" void kernel_launch(void* const* d_in, const int* in_sizes, int n_in,
                              void* d_out, int out_size) {
    const float* x = (const float*)d_in[0];
    const float* w = (const float*)d_in[1];
    float* out = (float*)d_out;

    const int N = in_sizes[0];          // 33554432
    const int SIZE = N / 2;             // 16777216
    const int size4 = SIZE / 4;         // 4194304 float4 per half

    if (size4 % TPB == 0) {
        activation_kernel<false><<<size4 / TPB, TPB>>>(
            (const float4*)x, (const float4*)w, (float4*)out, size4);
    } else {
        activation_kernel<true><<<(size4 + TPB - 1) / TPB, TPB>>>(
            (const float4*)x, (const float4*)w, (float4*)out, size4);
    }
}

// round 13
// speedup vs baseline: 1.0078x; 1.0078x over previous
#include <cuda_runtime.h>

// activation_moduleA: out[0:SIZE] = p = x[0:SIZE]
//                     out[SIZE:N] = weight * selu(p) + q,  q = x[SIZE:N]
// selu(v) = SCALE * (v > 0 ? v : ALPHA*(exp(v)-1))
//
// FINAL (convergence re-bench of the R10 session-best, 52.96 us):
// HBM-streaming-bound op. ~320 MB mandatory logical traffic (~281 MB DRAM
// after natural L2 absorption across graph replays), pinned at the chip's
// effective mixed-R/W streaming ceiling (~6.3-6.4 TB/s, 79-81% of spec).
// Tested and rejected as neutral: deeper MLP (U=4), occupancy trades,
// __ldcs/__stcs/__ldlu cache-hint policies, PTX evict hints (unsupported),
// TPB 256 vs 512. Shape: TPB=512, one float4-tile per thread, plain
// LDG.128/STG.128, guard-free exact-division path, regs 31, occ ~76%.

#define SELU_SCALE 1.0507009873554804934193349852946f
#define SELU_ALPHA 1.6732632423543772848170429916717f

#define TPB 512

__device__ __forceinline__ float selu_f(float v) {
    float neg = SELU_ALPHA * expm1f(v);
    return SELU_SCALE * (v > 0.0f ? v : neg);
}

template <bool GUARD>
__global__ void __launch_bounds__(TPB)
activation_kernel(const float4* __restrict__ x,
                  const float4* __restrict__ w,
                  float4* __restrict__ out,
                  int size4)   // SIZE/4 float4 elements per half
{
    int i = blockIdx.x * TPB + threadIdx.x;
    if (GUARD && i >= size4) return;

    float4 p  = x[i];
    float4 q  = x[i + size4];
    float4 wv = w[i];

    // first half: straight copy of p (store issues while SELU computes)
    out[i] = p;

    float4 r;
    r.x = fmaf(wv.x, selu_f(p.x), q.x);
    r.y = fmaf(wv.y, selu_f(p.y), q.y);
    r.z = fmaf(wv.z, selu_f(p.z), q.z);
    r.w = fmaf(wv.w, selu_f(p.w), q.w);
    out[i + size4] = r;
}

extern "C" void kernel_launch(void* const* d_in, const int* in_sizes, int n_in,
                              void* d_out, int out_size) {
    const float* x = (const float*)d_in[0];
    const float* w = (const float*)d_in[1];
    float* out = (float*)d_out;

    const int N = in_sizes[0];          // 33554432
    const int SIZE = N / 2;             // 16777216
    const int size4 = SIZE / 4;         // 4194304 float4 per half

    if (size4 % TPB == 0) {
        // exact division: no per-thread bounds guard (hit for this problem)
        activation_kernel<false><<<size4 / TPB, TPB>>>(
            (const float4*)x, (const float4*)w, (float4*)out, size4);
    } else {
        activation_kernel<true><<<(size4 + TPB - 1) / TPB, TPB>>>(
            (const float4*)x, (const float4*)w, (float4*)out, size4);
    }
}